// round 2
// baseline (speedup 1.0000x reference)
#include <cuda_runtime.h>
#include <cuda_bf16.h>
#include <math.h>

// Problem constants
#define MAXE 500000
#define CC 128          // C
#define HH 256          // H
#define ED 72           // EDGE_DIM = 8 * 9
#define EDP 80          // padded K for GEMM1
#define CUTOFF_F 6.0f
#define EPS_F 1e-9f

// -------- device scratch (static, no allocation) --------
__device__ int g_nact;
__device__ int g_ninact;
__device__ int g_active[MAXE];
__device__ int g_inactive[MAXE];
__device__ float g_const_row[CC];

// -------- f32x2 packed helpers --------
__device__ __forceinline__ unsigned long long pk2(float lo, float hi) {
    unsigned long long u;
    asm("mov.b64 %0, {%1, %2};" : "=l"(u) : "f"(lo), "f"(hi));
    return u;
}
__device__ __forceinline__ float2 upk2(unsigned long long u) {
    float lo, hi;
    asm("mov.b64 {%0, %1}, %2;" : "=f"(lo), "=f"(hi) : "l"(u));
    return make_float2(lo, hi);
}
__device__ __forceinline__ void ffma2(unsigned long long &d, unsigned long long a, unsigned long long b) {
    asm("fma.rn.f32x2 %0, %1, %2, %0;" : "+l"(d) : "l"(a), "l"(b));
}

__device__ __forceinline__ float silu_f(float x) {
    return x / (1.0f + expf(-x));
}

__device__ __forceinline__ void warp_reduce2(float &s, float &q) {
#pragma unroll
    for (int o = 16; o > 0; o >>= 1) {
        s += __shfl_xor_sync(0xffffffffu, s, o);
        q += __shfl_xor_sync(0xffffffffu, q, o);
    }
}

// -------- kernel 0: reset counters --------
__global__ void reset_kernel() {
    g_nact = 0;
    g_ninact = 0;
}

// -------- kernel 1: constant output row for zero-feature edges --------
__global__ __launch_bounds__(256) void const_row_kernel(
    const float* __restrict__ b1, const float* __restrict__ W2, const float* __restrict__ b2,
    const float* __restrict__ W3, const float* __restrict__ b3,
    const float* __restrict__ eln_w, const float* __restrict__ eln_b)
{
    __shared__ float s1[HH];
    __shared__ float s2[HH];
    __shared__ float stats[2];
    int t = threadIdx.x;

    s1[t] = silu_f(b1[t]);
    __syncthreads();

    float acc = b2[t];
    for (int k = 0; k < HH; k++) acc += s1[k] * W2[k * HH + t];
    s2[t] = silu_f(acc);
    __syncthreads();

    float val = 0.0f;
    if (t < CC) {
        acc = b3[t];
        for (int k = 0; k < HH; k++) acc += s2[k] * W3[k * CC + t];
        val = acc;
        s1[t] = val;
    }
    __syncthreads();
    if (t == 0) {
        float s = 0.f, sq = 0.f;
        for (int k = 0; k < CC; k++) { s += s1[k]; sq += s1[k] * s1[k]; }
        float mu = s * (1.0f / CC);
        float var = sq * (1.0f / CC) - mu * mu;
        stats[0] = mu;
        stats[1] = rsqrtf(var + 1e-5f);
    }
    __syncthreads();
    if (t < CC) g_const_row[t] = (val - stats[0]) * stats[1] * eln_w[t] + eln_b[t];
}

// -------- kernel 2: node embedding layernorm (warp per row) --------
__global__ __launch_bounds__(256) void node_kernel(
    const int* __restrict__ Z, const float* __restrict__ zt,
    const float* __restrict__ w, const float* __restrict__ b,
    float* __restrict__ out, int N)
{
    int row = blockIdx.x * 8 + (threadIdx.x >> 5);
    int lane = threadIdx.x & 31;
    if (row >= N) return;
    int zi = Z[row];
    float4 v = *(const float4*)(zt + (size_t)zi * CC + lane * 4);
    float s = v.x + v.y + v.z + v.w;
    float q = v.x * v.x + v.y * v.y + v.z * v.z + v.w * v.w;
    warp_reduce2(s, q);
    float mu = s * (1.0f / CC);
    float var = q * (1.0f / CC) - mu * mu;
    float rs = rsqrtf(var + 1e-5f);
    float4 wv = *(const float4*)(w + lane * 4);
    float4 bv = *(const float4*)(b + lane * 4);
    float4 o;
    o.x = (v.x - mu) * rs * wv.x + bv.x;
    o.y = (v.y - mu) * rs * wv.y + bv.y;
    o.z = (v.z - mu) * rs * wv.z + bv.z;
    o.w = (v.w - mu) * rs * wv.w + bv.w;
    *(float4*)(out + (size_t)row * CC + lane * 4) = o;
}

// -------- kernel 3: classify edges into active / inactive lists --------
__global__ __launch_bounds__(256) void prep_kernel(
    const float* __restrict__ pos, const int* __restrict__ snd,
    const int* __restrict__ rcv, int E)
{
    int i = blockIdx.x * blockDim.x + threadIdx.x;
    if (i >= E) return;
    int s = snd[i], r = rcv[i];
    float dx = pos[3 * r + 0] - pos[3 * s + 0];
    float dy = pos[3 * r + 1] - pos[3 * s + 1];
    float dz = pos[3 * r + 2] - pos[3 * s + 2];
    float d = sqrtf(dx * dx + dy * dy + dz * dz);
    if (d < CUTOFF_F) {
        int k = atomicAdd(&g_nact, 1);
        g_active[k] = i;
    } else {
        int k = atomicAdd(&g_ninact, 1);
        g_inactive[k] = i;
    }
}

// -------- kernel 4: fill inactive edge rows with const row (warp per edge) --------
__global__ __launch_bounds__(256) void fill_kernel(float* __restrict__ out_edge)
{
    int gw = (blockIdx.x * blockDim.x + threadIdx.x) >> 5;
    int lane = threadIdx.x & 31;
    if (gw >= g_ninact) return;
    int e = g_inactive[gw];
    float4 v = *(const float4*)(g_const_row + lane * 4);
    *(float4*)(out_edge + (size_t)e * CC + lane * 4) = v;
}

// -------- fused tile GEMM on f32x2 --------
// A: smem column-major [KPAD][64]; W: global row-major [K][NOUT]; Bs: smem [16][128]
// Out: col-major stride 64 (OUT_RM=false) or row-major stride 132 (OUT_RM=true)
template<int K, int KPAD, int NOUT, bool SILU, bool OUT_RM>
__device__ __forceinline__ void tile_gemm(
    const float* __restrict__ A, const float* __restrict__ W,
    const float* __restrict__ bias, float* __restrict__ Bs,
    float* __restrict__ Out, int ty, int tx, int tid)
{
#pragma unroll
    for (int cb = 0; cb < NOUT; cb += 128) {
        unsigned long long acc[4][4];
#pragma unroll
        for (int i = 0; i < 4; i++)
#pragma unroll
            for (int p = 0; p < 4; p++) acc[i][p] = 0ULL;

        for (int k0 = 0; k0 < KPAD; k0 += 16) {
            __syncthreads();
#pragma unroll
            for (int t = 0; t < 8; t++) {
                int idx = tid + t * 256;
                int kk = idx >> 7, cc = idx & 127;
                int kg = k0 + kk;
                Bs[idx] = (kg < K) ? W[kg * NOUT + cb + cc] : 0.0f;
            }
            __syncthreads();
#pragma unroll
            for (int kk = 0; kk < 16; kk++) {
                float4 a  = *(const float4*)(A + (k0 + kk) * 64 + 4 * ty);
                float4 b0 = *(const float4*)(Bs + kk * 128 + 8 * tx);
                float4 b1 = *(const float4*)(Bs + kk * 128 + 8 * tx + 4);
                unsigned long long B0 = pk2(b0.x, b0.y), B1 = pk2(b0.z, b0.w);
                unsigned long long B2 = pk2(b1.x, b1.y), B3 = pk2(b1.z, b1.w);
                float av[4] = {a.x, a.y, a.z, a.w};
#pragma unroll
                for (int i = 0; i < 4; i++) {
                    unsigned long long A2 = pk2(av[i], av[i]);
                    ffma2(acc[i][0], A2, B0);
                    ffma2(acc[i][1], A2, B1);
                    ffma2(acc[i][2], A2, B2);
                    ffma2(acc[i][3], A2, B3);
                }
            }
        }
        // epilogue
#pragma unroll
        for (int p = 0; p < 4; p++) {
            int c0 = cb + 8 * tx + 2 * p;
            float bx = bias[c0], by = bias[c0 + 1];
#pragma unroll
            for (int i = 0; i < 4; i++) {
                float2 v = upk2(acc[i][p]);
                v.x += bx; v.y += by;
                if (SILU) { v.x = silu_f(v.x); v.y = silu_f(v.y); }
                int r = 4 * ty + i;
                if (OUT_RM) {
                    Out[r * 132 + c0]     = v.x;
                    Out[r * 132 + c0 + 1] = v.y;
                } else {
                    Out[c0 * 64 + r]       = v.x;
                    Out[(c0 + 1) * 64 + r] = v.y;
                }
            }
        }
    }
}

// smem layout (floats): sFeat 80*64=5120 | sHa 256*64=16384 | sHb 16384 | Bs 2048 | eidx 64 ints
#define SMEM_BYTES ((5120 + 16384 + 16384 + 2048) * 4 + 64 * 4)

// -------- kernel 5: fused edge MLP over active edges (64 edges per block) --------
__global__ __launch_bounds__(256) void mlp_kernel(
    const float* __restrict__ pos, const int* __restrict__ snd, const int* __restrict__ rcv,
    const float* __restrict__ W1, const float* __restrict__ b1,
    const float* __restrict__ W2, const float* __restrict__ b2,
    const float* __restrict__ W3, const float* __restrict__ b3,
    const float* __restrict__ eln_w, const float* __restrict__ eln_b,
    float* __restrict__ out_edge)
{
    extern __shared__ float smem[];
    float* sFeat = smem;                 // [80][64] col-major
    float* sHa   = smem + 5120;          // [256][64] col-major
    float* sHb   = sHa + 16384;          // [256][64] col-major
    float* Bs    = sHb + 16384;          // [16][128]
    int*   eidx  = (int*)(Bs + 2048);    // [64]
    float* sH3   = sHa;                  // alias: [64][132] row-major (8448 floats)

    int tid = threadIdx.x;
    int base = blockIdx.x * 64;
    int nact = g_nact;
    if (base >= nact) return;
    int count = min(64, nact - base);

    if (tid < 64) eidx[tid] = (tid < count) ? g_active[base + tid] : 0;
    __syncthreads();

    // ---- features: e = tid/4, part = tid%4 handles rbf {2p, 2p+1} x 9 sh ----
    {
        // zero pad rows 72..79 of sFeat
#pragma unroll
        for (int t = 0; t < 2; t++) sFeat[ED * 64 + tid + t * 256] = 0.0f;

        int e = tid >> 2;
        int part = tid & 3;
        if (e < count) {
            int ei = eidx[e];
            int s = snd[ei], r = rcv[ei];
            float vx = pos[3 * r + 0] - pos[3 * s + 0];
            float vy = pos[3 * r + 1] - pos[3 * s + 1];
            float vz = pos[3 * r + 2] - pos[3 * s + 2];
            float d = sqrtf(vx * vx + vy * vy + vz * vz);
            float inv = 1.0f / (d + EPS_F);
            float x = vx * inv, y = vy * inv, z = vz * inv;
            const float s3 = 1.7320508075688772f;
            const float s5 = 2.2360679774997896f;
            const float s15 = 3.8729833462074170f;
            float sh[9];
            sh[0] = 1.0f;
            sh[1] = s3 * x;
            sh[2] = s3 * y;
            sh[3] = s3 * z;
            sh[4] = s15 * x * y;
            sh[5] = s15 * y * z;
            sh[6] = 0.5f * s5 * (3.0f * z * z - 1.0f);
            sh[7] = s15 * x * z;
            sh[8] = 0.5f * s15 * (x * x - y * y);
            float xd = d * (1.0f / CUTOFF_F);
            float xp = xd * xd; xp = xp * xp;                // x^4
            float env = 1.0f - 15.0f * xp + 24.0f * xp * xd - 10.0f * xp * xd * xd;
            const float pref = 0.5773502691896258f;          // sqrt(2/6)
            const float PI_F = 3.14159265358979323846f;
#pragma unroll
            for (int q = 0; q < 2; q++) {
                int nb = part * 2 + q;                       // rbf index 0..7
                float n = (float)(nb + 1);
                float rb = pref * sinf(n * PI_F * d * (1.0f / CUTOFF_F)) * inv;
                float re = rb * env;
#pragma unroll
                for (int m = 0; m < 9; m++)
                    sFeat[(nb * 9 + m) * 64 + e] = re * sh[m];
            }
        }
    }
    __syncthreads();

    int ty = tid >> 4;   // 0..15 -> rows 4ty..4ty+3
    int tx = tid & 15;   // 0..15 -> cols 8tx..8tx+7

    tile_gemm<ED, EDP, HH, true,  false>(sFeat, W1, b1, Bs, sHa, ty, tx, tid);
    tile_gemm<HH, HH,  HH, true,  false>(sHa,   W2, b2, Bs, sHb, ty, tx, tid);
    tile_gemm<HH, HH,  CC, false, true >(sHb,   W3, b3, Bs, sH3, ty, tx, tid);
    __syncthreads();

    // ---- layernorm + scatter write (8 warps x 8 rows) ----
    int w = tid >> 5, lane = tid & 31;
#pragma unroll
    for (int rr = 0; rr < 8; rr++) {
        int r = w * 8 + rr;
        if (r >= count) continue;
        float4 v = *(const float4*)(sH3 + r * 132 + lane * 4);
        float s = v.x + v.y + v.z + v.w;
        float q = v.x * v.x + v.y * v.y + v.z * v.z + v.w * v.w;
        warp_reduce2(s, q);
        float mu = s * (1.0f / CC);
        float var = q * (1.0f / CC) - mu * mu;
        float rs = rsqrtf(var + 1e-5f);
        float4 wv = *(const float4*)(eln_w + lane * 4);
        float4 bv = *(const float4*)(eln_b + lane * 4);
        float4 o;
        o.x = (v.x - mu) * rs * wv.x + bv.x;
        o.y = (v.y - mu) * rs * wv.y + bv.y;
        o.z = (v.z - mu) * rs * wv.z + bv.z;
        o.w = (v.w - mu) * rs * wv.w + bv.w;
        int e = eidx[r];
        *(float4*)(out_edge + (size_t)e * CC + lane * 4) = o;
    }
}

// -------- launch --------
extern "C" void kernel_launch(void* const* d_in, const int* in_sizes, int n_in,
                              void* d_out, int out_size)
{
    const int*   Z     = (const int*)  d_in[0];
    const float* pos   = (const float*)d_in[1];
    const int*   snd   = (const int*)  d_in[2];
    const int*   rcv   = (const int*)  d_in[3];
    const float* zt    = (const float*)d_in[4];
    const float* zln_w = (const float*)d_in[5];
    const float* zln_b = (const float*)d_in[6];
    const float* W1    = (const float*)d_in[7];
    const float* b1    = (const float*)d_in[8];
    const float* W2    = (const float*)d_in[9];
    const float* b2    = (const float*)d_in[10];
    const float* W3    = (const float*)d_in[11];
    const float* b3    = (const float*)d_in[12];
    const float* eln_w = (const float*)d_in[13];
    const float* eln_b = (const float*)d_in[14];

    int N = in_sizes[0];
    int E = in_sizes[2];

    float* out_node = (float*)d_out;
    float* out_edge = out_node + (size_t)N * CC;

    cudaFuncSetAttribute(mlp_kernel, cudaFuncAttributeMaxDynamicSharedMemorySize, SMEM_BYTES);

    reset_kernel<<<1, 1>>>();
    const_row_kernel<<<1, 256>>>(b1, W2, b2, W3, b3, eln_w, eln_b);
    node_kernel<<<(N + 7) / 8, 256>>>(Z, zt, zln_w, zln_b, out_node, N);
    prep_kernel<<<(E + 255) / 256, 256>>>(pos, snd, rcv, E);
    fill_kernel<<<(E + 7) / 8, 256>>>(out_edge);
    mlp_kernel<<<(E + 63) / 64, 256, SMEM_BYTES>>>(pos, snd, rcv,
                                                   W1, b1, W2, b2, W3, b3,
                                                   eln_w, eln_b, out_edge);
}

// round 4
// speedup vs baseline: 3.9958x; 3.9958x over previous
#include <cuda_runtime.h>
#include <cuda_bf16.h>
#include <cstdint>
#include <math.h>

#define MAXE 500000
#define CC 128
#define HH 256
#define ED 72
#define CUTOFF_F 6.0f
#define EPS_F 1e-9f

// 30 weight stages of 16KB each (k32 x n128, fragment-packed, tf32-rounded)
// stages 0-5: W1 (np0 kp0..2, np1 kp0..2)   [K padded 72->96]
// stages 6-21: W2 (np0 kp0..7, np1 kp0..7)
// stages 22-29: W3 (np0 kp0..7)
#define NSTAGES 30

__device__ int g_nact;
__device__ int g_ninact;
__device__ int g_active[MAXE];
__device__ int g_inactive[MAXE];
__device__ float g_const_row[CC];
__device__ __align__(16) float g_Wpk[NSTAGES * 4096];

// ---------------- helpers ----------------
__device__ __forceinline__ uint32_t smem_u32(const void* p) {
    uint32_t a;
    asm("{ .reg .u64 t; cvta.to.shared.u64 t, %1; cvt.u32.u64 %0, t; }" : "=r"(a) : "l"(p));
    return a;
}
__device__ __forceinline__ uint32_t rna_tf32_bits(float x) {
    uint32_t u;
    asm("cvt.rna.tf32.f32 %0, %1;" : "=r"(u) : "f"(x));
    return u;
}
__device__ __forceinline__ void mma8(float c[4], uint4 a, uint32_t b0, uint32_t b1) {
    asm volatile(
        "mma.sync.aligned.m16n8k8.row.col.f32.tf32.tf32.f32 "
        "{%0,%1,%2,%3},{%4,%5,%6,%7},{%8,%9},{%0,%1,%2,%3};"
        : "+f"(c[0]), "+f"(c[1]), "+f"(c[2]), "+f"(c[3])
        : "r"(a.x), "r"(a.y), "r"(a.z), "r"(a.w), "r"(b0), "r"(b1));
}
__device__ __forceinline__ float silu_fast(float x) {
    float xc = fminf(fmaxf(x, -30.0f), 30.0f);
    float t = __expf(-xc);
    float z = 1.0f + t;
    float r = __uint_as_float(0x7EF127EAu - __float_as_uint(z));
    r = r * (2.0f - z * r);
    r = r * (2.0f - z * r);
    return x * r;
}
__device__ __forceinline__ float silu_exact(float x) { return x / (1.0f + expf(-x)); }
__device__ __forceinline__ void warp_red2(float &s, float &q) {
#pragma unroll
    for (int o = 16; o > 0; o >>= 1) {
        s += __shfl_xor_sync(0xffffffffu, s, o);
        q += __shfl_xor_sync(0xffffffffu, q, o);
    }
}

// ---------------- small kernels ----------------
__global__ void reset_kernel() { g_nact = 0; g_ninact = 0; }

// pack weights into fragment layout, tf32-rounded
__global__ __launch_bounds__(256) void prepw_kernel(
    const float* __restrict__ W1, const float* __restrict__ W2, const float* __restrict__ W3)
{
    int i = blockIdx.x * 256 + threadIdx.x;   // 30*4096 = 122880 total
    int s = i >> 12, e = i & 4095;
    int wc = e >> 10;
    int r = e & 1023;
    int ks = r >> 8;
    int r2 = r & 255;
    int nt = r2 >> 6;
    int r3 = r2 & 63;
    int lane = r3 >> 1, j = r3 & 1;
    int k_loc = ks * 8 + (lane & 3) + j * 4;
    int n_loc = wc * 32 + nt * 8 + (lane >> 2);
    float v;
    if (s < 6) {
        int np = s / 3, kp = s % 3;
        int k = kp * 32 + k_loc, n = np * 128 + n_loc;
        v = (k < ED) ? W1[k * HH + n] : 0.0f;
    } else if (s < 22) {
        int t = s - 6, np = t >> 3, kp = t & 7;
        int k = kp * 32 + k_loc, n = np * 128 + n_loc;
        v = W2[k * HH + n];
    } else {
        int t = s - 22, kp = t;
        int k = kp * 32 + k_loc, n = n_loc;
        v = W3[k * CC + n];
    }
    ((uint32_t*)g_Wpk)[i] = rna_tf32_bits(v);
}

__global__ __launch_bounds__(256) void const_row_kernel(
    const float* __restrict__ b1, const float* __restrict__ W2, const float* __restrict__ b2,
    const float* __restrict__ W3, const float* __restrict__ b3,
    const float* __restrict__ eln_w, const float* __restrict__ eln_b)
{
    __shared__ float s1[HH], s2[HH], stats[2];
    int t = threadIdx.x;
    s1[t] = silu_exact(b1[t]);
    __syncthreads();
    float acc = b2[t];
    for (int k = 0; k < HH; k++) acc += s1[k] * W2[k * HH + t];
    s2[t] = silu_exact(acc);
    __syncthreads();
    float val = 0.0f;
    if (t < CC) {
        acc = b3[t];
        for (int k = 0; k < HH; k++) acc += s2[k] * W3[k * CC + t];
        val = acc; s1[t] = val;
    }
    __syncthreads();
    if (t == 0) {
        float s = 0.f, sq = 0.f;
        for (int k = 0; k < CC; k++) { s += s1[k]; sq += s1[k] * s1[k]; }
        float mu = s / CC, var = sq / CC - mu * mu;
        stats[0] = mu; stats[1] = rsqrtf(var + 1e-5f);
    }
    __syncthreads();
    if (t < CC) g_const_row[t] = (val - stats[0]) * stats[1] * eln_w[t] + eln_b[t];
}

__global__ __launch_bounds__(256) void node_kernel(
    const int* __restrict__ Z, const float* __restrict__ zt,
    const float* __restrict__ w, const float* __restrict__ b,
    float* __restrict__ out, int N)
{
    int row = blockIdx.x * 8 + (threadIdx.x >> 5);
    int lane = threadIdx.x & 31;
    if (row >= N) return;
    float4 v = *(const float4*)(zt + (size_t)Z[row] * CC + lane * 4);
    float s = v.x + v.y + v.z + v.w;
    float q = v.x * v.x + v.y * v.y + v.z * v.z + v.w * v.w;
    warp_red2(s, q);
    float mu = s / CC, var = q / CC - mu * mu, rs = rsqrtf(var + 1e-5f);
    float4 wv = *(const float4*)(w + lane * 4);
    float4 bv = *(const float4*)(b + lane * 4);
    float4 o;
    o.x = (v.x - mu) * rs * wv.x + bv.x; o.y = (v.y - mu) * rs * wv.y + bv.y;
    o.z = (v.z - mu) * rs * wv.z + bv.z; o.w = (v.w - mu) * rs * wv.w + bv.w;
    *(float4*)(out + (size_t)row * CC + lane * 4) = o;
}

__global__ __launch_bounds__(256) void prep_kernel(
    const float* __restrict__ pos, const int* __restrict__ snd,
    const int* __restrict__ rcv, int E)
{
    int i = blockIdx.x * blockDim.x + threadIdx.x;
    if (i >= E) return;
    int s = snd[i], r = rcv[i];
    float dx = pos[3 * r] - pos[3 * s], dy = pos[3 * r + 1] - pos[3 * s + 1], dz = pos[3 * r + 2] - pos[3 * s + 2];
    float d = sqrtf(dx * dx + dy * dy + dz * dz);
    if (d < CUTOFF_F) { g_active[atomicAdd(&g_nact, 1)] = i; }
    else              { g_inactive[atomicAdd(&g_ninact, 1)] = i; }
}

__global__ __launch_bounds__(256) void fill_kernel(float* __restrict__ out_edge)
{
    int gw = (blockIdx.x * blockDim.x + threadIdx.x) >> 5;
    int lane = threadIdx.x & 31;
    if (gw >= g_ninact) return;
    int e = g_inactive[gw];
    float4 v = *(const float4*)(g_const_row + lane * 4);
    *(float4*)(out_edge + (size_t)e * CC + lane * 4) = v;
}

// ---------------- fused MLP kernel (mma.sync tf32) ----------------
// SMEM float offsets
#define RING_F  0        // 3 * 4096
#define A2_F    12288    // 16384 (also SOUT after GEMM2)
#define A3_F    28672    // 16384
#define A1_F    45056    // 6144
#define B1_F    51200
#define B2_F    51456
#define B3_F    51712
#define ELNW_F  51840
#define ELNB_F  51968
#define EIDX_F  52096    // 64 ints
#define SMEM_F  52160
#define SMEM_BYTES (SMEM_F * 4)

__device__ __forceinline__ void issue_stage(uint32_t ring_u32, int s, int tid) {
    if (s < NSTAGES) {
        uint32_t dst = ring_u32 + (uint32_t)(s % 3) * 16384u + (uint32_t)tid * 16u;
        const float* src = g_Wpk + s * 4096 + tid * 4;
#pragma unroll
        for (int i = 0; i < 4; i++) {
            asm volatile("cp.async.cg.shared.global [%0], [%1], 16;"
                         :: "r"(dst + i * 4096u), "l"(src + i * 1024) : "memory");
        }
    }
    asm volatile("cp.async.commit_group;" ::: "memory");
}
#define CPWAIT2() asm volatile("cp.async.wait_group 2;" ::: "memory")

__device__ __forceinline__ void gemm_run(
    const float* __restrict__ Abuf, int AKS, int nkp,
    float* __restrict__ smem, uint32_t ring_u32, int &st,
    int tid, int mt0, int mt1, int wc, int lane,
    float acc[2][4][4])
{
    for (int kp = 0; kp < nkp; kp++) {
        CPWAIT2();
        __syncthreads();
        const float* ringbuf = smem + (st % 3) * 4096;
#pragma unroll
        for (int kk = 0; kk < 4; kk++) {
            int ksA = kp * 4 + kk;
            uint4 a0 = *(const uint4*)(Abuf + ((mt0 * AKS + ksA) * 32 + lane) * 4);
            uint4 a1 = *(const uint4*)(Abuf + ((mt1 * AKS + ksA) * 32 + lane) * 4);
            const float* bp = ringbuf + wc * 1024 + kk * 256 + lane * 2;
#pragma unroll
            for (int nt = 0; nt < 4; nt++) {
                uint2 b = *(const uint2*)(bp + nt * 64);
                mma8(acc[0][nt], a0, b.x, b.y);
                mma8(acc[1][nt], a1, b.x, b.y);
            }
        }
        __syncthreads();
        issue_stage(ring_u32, st + 3, tid);
        st++;
    }
}

// epilogue: acc + bias -> silu -> tf32 -> A-fragment layout (AKS=32) at column offset np*128
__device__ __forceinline__ void epi_silu(
    float acc[2][4][4], int np, const float* __restrict__ bs,
    uint32_t* __restrict__ Adst, int mg, int wc, int lane)
{
#pragma unroll
    for (int mi = 0; mi < 2; mi++) {
        int mbase = (2 * mg + mi) * 16;
#pragma unroll
        for (int nt = 0; nt < 4; nt++) {
            int cbase = wc * 32 + nt * 8 + 2 * (lane & 3);
#pragma unroll
            for (int i = 0; i < 4; i++) {
                int r = mbase + (lane >> 2) + ((i >> 1) << 3);
                int cc = cbase + (i & 1);
                float v = silu_fast(acc[mi][nt][i] + bs[np * 128 + cc]);
                int k = np * 128 + cc;
                int off = (((r >> 4) * 32 + (k >> 3)) * 32 + (((r & 7) << 2) | (k & 3))) * 4
                          + (((k >> 2) & 1) << 1) + ((r >> 3) & 1);
                Adst[off] = rna_tf32_bits(v);
            }
        }
    }
}

__global__ __launch_bounds__(256, 1) void mlp_kernel(
    const float* __restrict__ pos, const int* __restrict__ snd, const int* __restrict__ rcv,
    const float* __restrict__ b1, const float* __restrict__ b2, const float* __restrict__ b3,
    const float* __restrict__ eln_w, const float* __restrict__ eln_b,
    float* __restrict__ out_edge)
{
    extern __shared__ float smem[];
    int tid = threadIdx.x;
    int wid = tid >> 5, lane = tid & 31;
    int base = blockIdx.x * 64;
    int nact = g_nact;
    if (base >= nact) return;
    int count = min(64, nact - base);

    uint32_t ring_u32 = smem_u32(smem);
    int* eidx = (int*)(smem + EIDX_F);

    // init smem
    smem[B1_F + tid] = b1[tid];
    smem[B2_F + tid] = b2[tid];
    if (tid < 128) {
        smem[B3_F + tid]   = b3[tid];
        smem[ELNW_F + tid] = eln_w[tid];
        smem[ELNB_F + tid] = eln_b[tid];
    }
    if (tid < 64) eidx[tid] = (tid < count) ? g_active[base + tid] : 0;
    // zero A1 (features buffer, 6144 floats)
#pragma unroll
    for (int i = 0; i < 6; i++)
        *(float4*)(smem + A1_F + (tid + i * 256) * 4) = make_float4(0.f, 0.f, 0.f, 0.f);
    __syncthreads();

    // start weight pipeline
    issue_stage(ring_u32, 0, tid);
    issue_stage(ring_u32, 1, tid);
    issue_stage(ring_u32, 2, tid);

    // ---- features -> A1 fragment layout (AKS=12, K=96 padded) ----
    {
        int e = tid >> 2;
        int part = tid & 3;
        if (e < count) {
            int ei = eidx[e];
            int ss = snd[ei], rr = rcv[ei];
            float vx = pos[3 * rr] - pos[3 * ss];
            float vy = pos[3 * rr + 1] - pos[3 * ss + 1];
            float vz = pos[3 * rr + 2] - pos[3 * ss + 2];
            float d = sqrtf(vx * vx + vy * vy + vz * vz);
            float inv = 1.0f / (d + EPS_F);
            float x = vx * inv, y = vy * inv, z = vz * inv;
            const float s3 = 1.7320508075688772f, s5 = 2.2360679774997896f, s15 = 3.8729833462074170f;
            float sh[9];
            sh[0] = 1.0f; sh[1] = s3 * x; sh[2] = s3 * y; sh[3] = s3 * z;
            sh[4] = s15 * x * y; sh[5] = s15 * y * z;
            sh[6] = 0.5f * s5 * (3.0f * z * z - 1.0f);
            sh[7] = s15 * x * z; sh[8] = 0.5f * s15 * (x * x - y * y);
            float xd = d * (1.0f / CUTOFF_F);
            float xp = xd * xd; xp = xp * xp;
            float env = 1.0f - 15.0f * xp + 24.0f * xp * xd - 10.0f * xp * xd * xd;
            const float pref = 0.5773502691896258f;
            const float PI_F = 3.14159265358979323846f;
            uint32_t* A1u = (uint32_t*)(smem + A1_F);
#pragma unroll
            for (int q = 0; q < 2; q++) {
                int nb = part * 2 + q;
                float rb = pref * __sinf((float)(nb + 1) * PI_F * xd) * inv;
                float re = rb * env;
#pragma unroll
                for (int m = 0; m < 9; m++) {
                    int k = nb * 9 + m;
                    float val = re * sh[m];
                    int off = (((e >> 4) * 12 + (k >> 3)) * 32 + (((e & 7) << 2) | (k & 3))) * 4
                              + (((k >> 2) & 1) << 1) + ((e >> 3) & 1);
                    A1u[off] = rna_tf32_bits(val);
                }
            }
        }
    }

    int mg = wid & 1;        // m-group: rows mg*32 .. mg*32+31
    int wc = wid >> 1;       // n-group: cols wc*32 .. wc*32+31
    int mt0 = 2 * mg, mt1 = 2 * mg + 1;

    float acc[2][4][4];
    int st = 0;

    // ---- GEMM1: A1[64x96] x W1 -> silu -> A2 (K out = 256) ----
#pragma unroll 1
    for (int np = 0; np < 2; np++) {
#pragma unroll
        for (int a = 0; a < 2; a++)
#pragma unroll
            for (int b = 0; b < 4; b++)
#pragma unroll
                for (int c = 0; c < 4; c++) acc[a][b][c] = 0.0f;
        gemm_run(smem + A1_F, 12, 3, smem, ring_u32, st, tid, mt0, mt1, wc, lane, acc);
        epi_silu(acc, np, smem + B1_F, (uint32_t*)(smem + A2_F), mg, wc, lane);
    }

    // ---- GEMM2: A2[64x256] x W2 -> silu -> A3 ----
#pragma unroll 1
    for (int np = 0; np < 2; np++) {
#pragma unroll
        for (int a = 0; a < 2; a++)
#pragma unroll
            for (int b = 0; b < 4; b++)
#pragma unroll
                for (int c = 0; c < 4; c++) acc[a][b][c] = 0.0f;
        gemm_run(smem + A2_F, 32, 8, smem, ring_u32, st, tid, mt0, mt1, wc, lane, acc);
        epi_silu(acc, np, smem + B2_F, (uint32_t*)(smem + A3_F), mg, wc, lane);
    }

    // ---- GEMM3: A3[64x256] x W3 -> +b3 -> SOUT (A2 region reused) ----
#pragma unroll
    for (int a = 0; a < 2; a++)
#pragma unroll
        for (int b = 0; b < 4; b++)
#pragma unroll
            for (int c = 0; c < 4; c++) acc[a][b][c] = 0.0f;
    gemm_run(smem + A3_F, 32, 8, smem, ring_u32, st, tid, mt0, mt1, wc, lane, acc);

    float* SOUT = smem + A2_F;   // [64][132]
#pragma unroll
    for (int mi = 0; mi < 2; mi++) {
        int mbase = (2 * mg + mi) * 16;
#pragma unroll
        for (int nt = 0; nt < 4; nt++) {
            int cbase = wc * 32 + nt * 8 + 2 * (lane & 3);
#pragma unroll
            for (int i = 0; i < 4; i++) {
                int r = mbase + (lane >> 2) + ((i >> 1) << 3);
                int cc = cbase + (i & 1);
                SOUT[r * 132 + cc] = acc[mi][nt][i] + smem[B3_F + cc];
            }
        }
    }
    __syncthreads();

    // ---- layernorm + scatter: warp w handles rows 8w..8w+7 ----
#pragma unroll
    for (int rr = 0; rr < 8; rr++) {
        int row = wid * 8 + rr;
        if (row >= count) continue;
        float4 v = *(const float4*)(SOUT + row * 132 + lane * 4);
        float s = v.x + v.y + v.z + v.w;
        float q = v.x * v.x + v.y * v.y + v.z * v.z + v.w * v.w;
        warp_red2(s, q);
        float mu = s * (1.0f / CC);
        float var = q * (1.0f / CC) - mu * mu;
        float rs = rsqrtf(var + 1e-5f);
        float4 wv = *(const float4*)(smem + ELNW_F + lane * 4);
        float4 bv = *(const float4*)(smem + ELNB_F + lane * 4);
        float4 o;
        o.x = (v.x - mu) * rs * wv.x + bv.x;
        o.y = (v.y - mu) * rs * wv.y + bv.y;
        o.z = (v.z - mu) * rs * wv.z + bv.z;
        o.w = (v.w - mu) * rs * wv.w + bv.w;
        *(float4*)(out_edge + (size_t)eidx[row] * CC + lane * 4) = o;
    }
}

// ---------------- launch ----------------
extern "C" void kernel_launch(void* const* d_in, const int* in_sizes, int n_in,
                              void* d_out, int out_size)
{
    const int*   Z     = (const int*)  d_in[0];
    const float* pos   = (const float*)d_in[1];
    const int*   snd   = (const int*)  d_in[2];
    const int*   rcv   = (const int*)  d_in[3];
    const float* zt    = (const float*)d_in[4];
    const float* zln_w = (const float*)d_in[5];
    const float* zln_b = (const float*)d_in[6];
    const float* W1    = (const float*)d_in[7];
    const float* b1    = (const float*)d_in[8];
    const float* W2    = (const float*)d_in[9];
    const float* b2    = (const float*)d_in[10];
    const float* W3    = (const float*)d_in[11];
    const float* b3    = (const float*)d_in[12];
    const float* eln_w = (const float*)d_in[13];
    const float* eln_b = (const float*)d_in[14];

    int N = in_sizes[0];
    int E = in_sizes[2];

    float* out_node = (float*)d_out;
    float* out_edge = out_node + (size_t)N * CC;

    cudaFuncSetAttribute(mlp_kernel, cudaFuncAttributeMaxDynamicSharedMemorySize, SMEM_BYTES);

    reset_kernel<<<1, 1>>>();
    prepw_kernel<<<480, 256>>>(W1, W2, W3);
    const_row_kernel<<<1, 256>>>(b1, W2, b2, W3, b3, eln_w, eln_b);
    node_kernel<<<(N + 7) / 8, 256>>>(Z, zt, zln_w, zln_b, out_node, N);
    prep_kernel<<<(E + 255) / 256, 256>>>(pos, snd, rcv, E);
    fill_kernel<<<(E + 7) / 8, 256>>>(out_edge);
    mlp_kernel<<<(E + 63) / 64, 256, SMEM_BYTES>>>(pos, snd, rcv,
                                                   b1, b2, b3, eln_w, eln_b, out_edge);
}

// round 5
// speedup vs baseline: 6.2731x; 1.5699x over previous
#include <cuda_runtime.h>
#include <cuda_fp16.h>
#include <cstdint>
#include <math.h>

#define MAXE 500000
#define CC 128
#define HH 256
#define ED 72
#define CUTOFF_F 6.0f
#define EPS_F 1e-9f

// 30 weight stages of 8KB each (k32 x n128 fp16, fragment-packed)
// s 0-5:  W1  np=s/3, kp=s%3   (K padded 72->96)
// s 6-21: W2  t=s-6: np=t>>3, kp=t&7
// s 22-29:W3  kp=s-22, np=0
#define NSTAGES 30

__device__ int g_nact;
__device__ int g_ninact;
__device__ int g_active[MAXE];
__device__ int g_inactive[MAXE];
__device__ float g_const_row[CC];
__device__ __align__(16) __half g_Wph[NSTAGES * 4096];

// ---------------- helpers ----------------
__device__ __forceinline__ uint32_t smem_u32(const void* p) {
    uint32_t a;
    asm("{ .reg .u64 t; cvta.to.shared.u64 t, %1; cvt.u32.u64 %0, t; }" : "=r"(a) : "l"(p));
    return a;
}
__device__ __forceinline__ uint32_t pack_h2(float lo, float hi) {
    uint32_t h;
    asm("cvt.rn.f16x2.f32 %0, %1, %2;" : "=r"(h) : "f"(hi), "f"(lo));
    return h;
}
__device__ __forceinline__ void mma16(float c[4], uint4 a, uint32_t b0, uint32_t b1) {
    asm volatile(
        "mma.sync.aligned.m16n8k16.row.col.f32.f16.f16.f32 "
        "{%0,%1,%2,%3},{%4,%5,%6,%7},{%8,%9},{%0,%1,%2,%3};"
        : "+f"(c[0]), "+f"(c[1]), "+f"(c[2]), "+f"(c[3])
        : "r"(a.x), "r"(a.y), "r"(a.z), "r"(a.w), "r"(b0), "r"(b1));
}
__device__ __forceinline__ float silu_fast(float x) {
    float xc = fminf(fmaxf(x, -30.0f), 30.0f);
    float t = __expf(-xc);
    float z = 1.0f + t;
    float r = __uint_as_float(0x7EF127EAu - __float_as_uint(z));
    r = r * (2.0f - z * r);
    r = r * (2.0f - z * r);
    return x * r;
}
__device__ __forceinline__ float silu_exact(float x) { return x / (1.0f + expf(-x)); }
__device__ __forceinline__ void warp_red2(float &s, float &q) {
#pragma unroll
    for (int o = 16; o > 0; o >>= 1) {
        s += __shfl_xor_sync(0xffffffffu, s, o);
        q += __shfl_xor_sync(0xffffffffu, q, o);
    }
}

// ---------------- small kernels ----------------
__global__ void reset_kernel() { g_nact = 0; g_ninact = 0; }

// pack weights into fp16 fragment layout
__global__ __launch_bounds__(256) void prepw_kernel(
    const float* __restrict__ W1, const float* __restrict__ W2, const float* __restrict__ W3)
{
    int i = blockIdx.x * 256 + threadIdx.x;   // 30*4096 = 122880
    if (i >= NSTAGES * 4096) return;
    int s = i >> 12, e = i & 4095;
    int h = e & 3;
    int lane = (e >> 2) & 31;
    int nt = (e >> 7) & 3;
    int kk = (e >> 9) & 1;
    int wcx = (e >> 10) & 3;
    int k_loc = kk * 16 + (h >> 1) * 8 + (lane & 3) * 2 + (h & 1);
    int n_loc = wcx * 32 + nt * 8 + (lane >> 2);
    float v;
    if (s < 6) {
        int np = s / 3, kp = s % 3;
        int k = kp * 32 + k_loc, n = np * 128 + n_loc;
        v = (k < ED) ? W1[k * HH + n] : 0.0f;
    } else if (s < 22) {
        int t = s - 6, np = t >> 3, kp = t & 7;
        int k = kp * 32 + k_loc, n = np * 128 + n_loc;
        v = W2[k * HH + n];
    } else {
        int kp = s - 22;
        int k = kp * 32 + k_loc;
        v = W3[k * CC + n_loc];
    }
    g_Wph[i] = __float2half_rn(v);
}

__global__ __launch_bounds__(256) void const_row_kernel(
    const float* __restrict__ b1, const float* __restrict__ W2, const float* __restrict__ b2,
    const float* __restrict__ W3, const float* __restrict__ b3,
    const float* __restrict__ eln_w, const float* __restrict__ eln_b)
{
    __shared__ float s1[HH], s2[HH], stats[2];
    int t = threadIdx.x;
    s1[t] = silu_exact(b1[t]);
    __syncthreads();
    float acc = b2[t];
    for (int k = 0; k < HH; k++) acc += s1[k] * W2[k * HH + t];
    s2[t] = silu_exact(acc);
    __syncthreads();
    float val = 0.0f;
    if (t < CC) {
        acc = b3[t];
        for (int k = 0; k < HH; k++) acc += s2[k] * W3[k * CC + t];
        val = acc; s1[t] = val;
    }
    __syncthreads();
    if (t == 0) {
        float s = 0.f, sq = 0.f;
        for (int k = 0; k < CC; k++) { s += s1[k]; sq += s1[k] * s1[k]; }
        float mu = s / CC, var = sq / CC - mu * mu;
        stats[0] = mu; stats[1] = rsqrtf(var + 1e-5f);
    }
    __syncthreads();
    if (t < CC) g_const_row[t] = (val - stats[0]) * stats[1] * eln_w[t] + eln_b[t];
}

__global__ __launch_bounds__(256) void node_kernel(
    const int* __restrict__ Z, const float* __restrict__ zt,
    const float* __restrict__ w, const float* __restrict__ b,
    float* __restrict__ out, int N)
{
    int row = blockIdx.x * 8 + (threadIdx.x >> 5);
    int lane = threadIdx.x & 31;
    if (row >= N) return;
    float4 v = *(const float4*)(zt + (size_t)Z[row] * CC + lane * 4);
    float s = v.x + v.y + v.z + v.w;
    float q = v.x * v.x + v.y * v.y + v.z * v.z + v.w * v.w;
    warp_red2(s, q);
    float mu = s / CC, var = q / CC - mu * mu, rs = rsqrtf(var + 1e-5f);
    float4 wv = *(const float4*)(w + lane * 4);
    float4 bv = *(const float4*)(b + lane * 4);
    float4 o;
    o.x = (v.x - mu) * rs * wv.x + bv.x; o.y = (v.y - mu) * rs * wv.y + bv.y;
    o.z = (v.z - mu) * rs * wv.z + bv.z; o.w = (v.w - mu) * rs * wv.w + bv.w;
    *(float4*)(out + (size_t)row * CC + lane * 4) = o;
}

__global__ __launch_bounds__(256) void prep_kernel(
    const float* __restrict__ pos, const int* __restrict__ snd,
    const int* __restrict__ rcv, int E)
{
    int i = blockIdx.x * blockDim.x + threadIdx.x;
    if (i >= E) return;
    int s = snd[i], r = rcv[i];
    float dx = pos[3 * r] - pos[3 * s], dy = pos[3 * r + 1] - pos[3 * s + 1], dz = pos[3 * r + 2] - pos[3 * s + 2];
    float d = sqrtf(dx * dx + dy * dy + dz * dz);
    if (d < CUTOFF_F) { g_active[atomicAdd(&g_nact, 1)] = i; }
    else              { g_inactive[atomicAdd(&g_ninact, 1)] = i; }
}

__global__ __launch_bounds__(256) void fill_kernel(float* __restrict__ out_edge)
{
    int gw = (blockIdx.x * blockDim.x + threadIdx.x) >> 5;
    int lane = threadIdx.x & 31;
    if (gw >= g_ninact) return;
    int e = g_inactive[gw];
    float4 v = *(const float4*)(g_const_row + lane * 4);
    *(float4*)(out_edge + (size_t)e * CC + lane * 4) = v;
}

// ---------------- fused MLP kernel (fp16 mma, 128 edges/CTA) ----------------
// SMEM byte offsets
#define RING_B   0        // 4 x 8192 = 32768
#define A2_B     32768    // 65536 (SOUT aliases here: 128*132*4 = 67584 <= A2+A1)
#define A1_B     98304    // 24576
#define A3_B     122880   // 65536
#define B1_B     188416   // 1024
#define B2_B     189440   // 1024
#define B3_B     190464   // 512
#define ELNW_B   190976   // 512
#define ELNB_B   191488   // 512
#define EIDX_B   192000   // 512
#define SMEM_BYTES 192512
#define SOUT_B   A2_B

__device__ __forceinline__ void issue_stage(uint32_t ring_u32, int s, int tid) {
    if (s < NSTAGES) {
        uint32_t dst = ring_u32 + (uint32_t)(s & 3) * 8192u + (uint32_t)tid * 32u;
        const char* src = (const char*)g_Wph + (size_t)s * 8192 + tid * 32;
        asm volatile("cp.async.cg.shared.global [%0], [%1], 16;" :: "r"(dst), "l"(src) : "memory");
        asm volatile("cp.async.cg.shared.global [%0], [%1], 16;" :: "r"(dst + 16u), "l"(src + 16) : "memory");
    }
    asm volatile("cp.async.commit_group;" ::: "memory");
}

__device__ __forceinline__ void gemm_run(
    const char* __restrict__ Abuf, int KS, int nkp,
    char* __restrict__ smc, uint32_t ring_u32, int &st,
    int tid, int mg, int wc, int lane, float acc[4][4][4])
{
    for (int kp = 0; kp < nkp; kp++) {
        asm volatile("cp.async.wait_group 2;" ::: "memory");
        __syncthreads();
        issue_stage(ring_u32, st + 3, tid);
        const char* bs = smc + RING_B + (st & 3) * 8192;
#pragma unroll
        for (int kk = 0; kk < 2; kk++) {
            int ksA = kp * 2 + kk;
            uint4 a[4];
#pragma unroll
            for (int mi = 0; mi < 4; mi++)
                a[mi] = *(const uint4*)(Abuf + (((4 * mg + mi) * KS + ksA) * 32 + lane) * 16);
#pragma unroll
            for (int nt = 0; nt < 4; nt++) {
                uint2 b = *(const uint2*)(bs + (((wc * 2 + kk) * 4 + nt) * 32 + lane) * 8);
#pragma unroll
                for (int mi = 0; mi < 4; mi++)
                    mma16(acc[mi][nt], a[mi], b.x, b.y);
            }
        }
        st++;
    }
}

// epilogue: acc + bias -> silu -> fp16 -> A-fragment layout (KS=16)
__device__ __forceinline__ void epi_silu(
    float acc[4][4][4], int np, const float* __restrict__ bs,
    char* __restrict__ Adst, int mg, int wc, int lane)
{
#pragma unroll
    for (int mi = 0; mi < 4; mi++) {
        int mt = 4 * mg + mi;
#pragma unroll
        for (int nt = 0; nt < 4; nt++) {
            int cb = np * 128 + wc * 32 + nt * 8 + 2 * (lane & 3);
            float v0 = silu_fast(acc[mi][nt][0] + bs[cb]);
            float v1 = silu_fast(acc[mi][nt][1] + bs[cb + 1]);
            float v2 = silu_fast(acc[mi][nt][2] + bs[cb]);
            float v3 = silu_fast(acc[mi][nt][3] + bs[cb + 1]);
            uint32_t h01 = pack_h2(v0, v1);
            uint32_t h23 = pack_h2(v2, v3);
            int ks = np * 8 + wc * 2 + (nt >> 1);
            uint32_t off = ((((mt * 16 + ks) * 32 + lane) * 4 + (nt & 1) * 2)) * 4u;
            *(uint2*)(Adst + off) = make_uint2(h01, h23);
        }
    }
}

__global__ __launch_bounds__(256, 1) void mlp_kernel(
    const float* __restrict__ pos, const int* __restrict__ snd, const int* __restrict__ rcv,
    const float* __restrict__ b1, const float* __restrict__ b2, const float* __restrict__ b3,
    const float* __restrict__ eln_w, const float* __restrict__ eln_b,
    float* __restrict__ out_edge)
{
    extern __shared__ char smc[];
    int tid = threadIdx.x;
    int wid = tid >> 5, lane = tid & 31;
    int base = blockIdx.x * 128;
    int nact = g_nact;
    if (base >= nact) return;
    int count = min(128, nact - base);

    uint32_t ring_u32 = smem_u32(smc);
    int* eidx = (int*)(smc + EIDX_B);
    float* B1s = (float*)(smc + B1_B);
    float* B2s = (float*)(smc + B2_B);
    float* B3s = (float*)(smc + B3_B);

    B1s[tid] = b1[tid];
    B2s[tid] = b2[tid];
    if (tid < 128) {
        B3s[tid] = b3[tid];
        ((float*)(smc + ELNW_B))[tid] = eln_w[tid];
        ((float*)(smc + ELNB_B))[tid] = eln_b[tid];
        eidx[tid] = (tid < count) ? g_active[base + tid] : 0;
    }
    // zero A1 (24576 B)
    {
        uint4 z = make_uint4(0, 0, 0, 0);
        uint4* a1z = (uint4*)(smc + A1_B);
#pragma unroll
        for (int i = 0; i < 6; i++) a1z[tid + i * 256] = z;
    }
    __syncthreads();

    issue_stage(ring_u32, 0, tid);
    issue_stage(ring_u32, 1, tid);
    issue_stage(ring_u32, 2, tid);

    // ---- features -> A1 fragment layout (2 threads per edge) ----
    {
        int e = tid >> 1, part = tid & 1;
        if (e < count) {
            int ei = eidx[e];
            int ss = snd[ei], rr = rcv[ei];
            float vx = pos[3 * rr] - pos[3 * ss];
            float vy = pos[3 * rr + 1] - pos[3 * ss + 1];
            float vz = pos[3 * rr + 2] - pos[3 * ss + 2];
            float d = sqrtf(vx * vx + vy * vy + vz * vz);
            float inv = 1.0f / (d + EPS_F);
            float x = vx * inv, y = vy * inv, z = vz * inv;
            const float s3 = 1.7320508075688772f, s5 = 2.2360679774997896f, s15 = 3.8729833462074170f;
            float sh[9];
            sh[0] = 1.0f; sh[1] = s3 * x; sh[2] = s3 * y; sh[3] = s3 * z;
            sh[4] = s15 * x * y; sh[5] = s15 * y * z;
            sh[6] = 0.5f * s5 * (3.0f * z * z - 1.0f);
            sh[7] = s15 * x * z; sh[8] = 0.5f * s15 * (x * x - y * y);
            float xd = d * (1.0f / CUTOFF_F);
            float xp = xd * xd; xp = xp * xp;
            float env = 1.0f - 15.0f * xp + 24.0f * xp * xd - 10.0f * xp * xd * xd;
            const float pref = 0.5773502691896258f;
            const float PI_F = 3.14159265358979323846f;
            float rbfe[8];
#pragma unroll
            for (int n = 0; n < 8; n++)
                rbfe[n] = pref * __sinf((float)(n + 1) * PI_F * xd) * inv * env;

            uint32_t* A1u = (uint32_t*)(smc + A1_B);
            int mt = e >> 4;
            int lnb = (e & 7) * 4;
            int ahi = (e & 15) >> 3;
            int nq = part ? 12 : 24;
            for (int kq = 0; kq < nq; kq++) {
                int k = part * 48 + kq * 2;
                float v0 = rbfe[k / 9] * sh[k % 9];
                float v1 = ((k + 1) < ED) ? rbfe[(k + 1) / 9] * sh[(k + 1) % 9] : 0.0f;
                uint32_t h = pack_h2(v0, v1);
                int ks = k >> 4;
                int ln = lnb + ((k & 7) >> 1);
                int reg = ((k & 15) >> 3) * 2 + ahi;
                A1u[((mt * 6 + ks) * 32 + ln) * 4 + reg] = h;
            }
        }
    }

    int mg = wid & 1;        // rows 64*mg .. 64*mg+63
    int wc = wid >> 1;       // cols 32*wc .. 32*wc+31
    float acc[4][4][4];
    int st = 0;

    // ---- GEMM1: A1[128x96] x W1 -> silu -> A2 ----
#pragma unroll 1
    for (int np = 0; np < 2; np++) {
#pragma unroll
        for (int a = 0; a < 4; a++)
#pragma unroll
            for (int b = 0; b < 4; b++)
#pragma unroll
                for (int c = 0; c < 4; c++) acc[a][b][c] = 0.0f;
        gemm_run(smc + A1_B, 6, 3, smc, ring_u32, st, tid, mg, wc, lane, acc);
        epi_silu(acc, np, B1s, smc + A2_B, mg, wc, lane);
    }

    // ---- GEMM2: A2[128x256] x W2 -> silu -> A3 ----
#pragma unroll 1
    for (int np = 0; np < 2; np++) {
#pragma unroll
        for (int a = 0; a < 4; a++)
#pragma unroll
            for (int b = 0; b < 4; b++)
#pragma unroll
                for (int c = 0; c < 4; c++) acc[a][b][c] = 0.0f;
        gemm_run(smc + A2_B, 16, 8, smc, ring_u32, st, tid, mg, wc, lane, acc);
        epi_silu(acc, np, B2s, smc + A3_B, mg, wc, lane);
    }

    // ---- GEMM3: A3[128x256] x W3 -> +b3 -> SOUT ----
#pragma unroll
    for (int a = 0; a < 4; a++)
#pragma unroll
        for (int b = 0; b < 4; b++)
#pragma unroll
            for (int c = 0; c < 4; c++) acc[a][b][c] = 0.0f;
    gemm_run(smc + A3_B, 16, 8, smc, ring_u32, st, tid, mg, wc, lane, acc);

    {
        float* SOUT = (float*)(smc + SOUT_B);   // [128][132]
#pragma unroll
        for (int mi = 0; mi < 4; mi++) {
            int r0 = (4 * mg + mi) * 16 + (lane >> 2);
#pragma unroll
            for (int nt = 0; nt < 4; nt++) {
                int cb = wc * 32 + nt * 8 + 2 * (lane & 3);
                SOUT[r0 * 132 + cb]           = acc[mi][nt][0] + B3s[cb];
                SOUT[r0 * 132 + cb + 1]       = acc[mi][nt][1] + B3s[cb + 1];
                SOUT[(r0 + 8) * 132 + cb]     = acc[mi][nt][2] + B3s[cb];
                SOUT[(r0 + 8) * 132 + cb + 1] = acc[mi][nt][3] + B3s[cb + 1];
            }
        }
    }
    __syncthreads();

    // ---- layernorm + scatter: warp w handles rows 16w..16w+15 ----
    {
        const float* SOUT = (const float*)(smc + SOUT_B);
        float4 wv = *(const float4*)((const float*)(smc + ELNW_B) + lane * 4);
        float4 bv = *(const float4*)((const float*)(smc + ELNB_B) + lane * 4);
#pragma unroll
        for (int rr = 0; rr < 16; rr++) {
            int row = wid * 16 + rr;
            if (row >= count) continue;
            float4 v = *(const float4*)(SOUT + row * 132 + lane * 4);
            float s = v.x + v.y + v.z + v.w;
            float q = v.x * v.x + v.y * v.y + v.z * v.z + v.w * v.w;
            warp_red2(s, q);
            float mu = s * (1.0f / CC);
            float var = q * (1.0f / CC) - mu * mu;
            float rs = rsqrtf(var + 1e-5f);
            float4 o;
            o.x = (v.x - mu) * rs * wv.x + bv.x;
            o.y = (v.y - mu) * rs * wv.y + bv.y;
            o.z = (v.z - mu) * rs * wv.z + bv.z;
            o.w = (v.w - mu) * rs * wv.w + bv.w;
            *(float4*)(out_edge + (size_t)eidx[row] * CC + lane * 4) = o;
        }
    }
}

// ---------------- launch ----------------
extern "C" void kernel_launch(void* const* d_in, const int* in_sizes, int n_in,
                              void* d_out, int out_size)
{
    const int*   Z     = (const int*)  d_in[0];
    const float* pos   = (const float*)d_in[1];
    const int*   snd   = (const int*)  d_in[2];
    const int*   rcv   = (const int*)  d_in[3];
    const float* zt    = (const float*)d_in[4];
    const float* zln_w = (const float*)d_in[5];
    const float* zln_b = (const float*)d_in[6];
    const float* W1    = (const float*)d_in[7];
    const float* b1    = (const float*)d_in[8];
    const float* W2    = (const float*)d_in[9];
    const float* b2    = (const float*)d_in[10];
    const float* W3    = (const float*)d_in[11];
    const float* b3    = (const float*)d_in[12];
    const float* eln_w = (const float*)d_in[13];
    const float* eln_b = (const float*)d_in[14];

    int N = in_sizes[0];
    int E = in_sizes[2];

    float* out_node = (float*)d_out;
    float* out_edge = out_node + (size_t)N * CC;

    cudaFuncSetAttribute(mlp_kernel, cudaFuncAttributeMaxDynamicSharedMemorySize, SMEM_BYTES);

    reset_kernel<<<1, 1>>>();
    prepw_kernel<<<480, 256>>>(W1, W2, W3);
    const_row_kernel<<<1, 256>>>(b1, W2, b2, W3, b3, eln_w, eln_b);
    node_kernel<<<(N + 7) / 8, 256>>>(Z, zt, zln_w, zln_b, out_node, N);
    prep_kernel<<<(E + 255) / 256, 256>>>(pos, snd, rcv, E);
    fill_kernel<<<(E + 7) / 8, 256>>>(out_edge);
    mlp_kernel<<<(E + 127) / 128, 256, SMEM_BYTES>>>(pos, snd, rcv,
                                                     b1, b2, b3, eln_w, eln_b, out_edge);
}